// round 16
// baseline (speedup 1.0000x reference)
#include <cuda_runtime.h>

typedef unsigned long long ull;

#define BATCH 32
#define NATOM 128
#define HH 64
#define WW 64
#define OH 57
#define SPP (OH*OH)           // 3249
#define NPS (NATOM*SPP)       // 415872
#define KSEL 256
#define NAL 17
#define CAP 2048
#define NBINS 4096
#define IMGPIX (HH*WW)        // 4096
#define NVEC (NPS/4)          // 103968 float4s
#define VCHUNK 2048           // float4s per collect chunk (51 chunks)
#define HSZ 1024

// ---------------- device state ----------------
__device__ float d_R[BATCH*IMGPIX];
__device__ float d_g[BATCH*NPS];              // ~53 MB
__device__ int   d_hist[BATCH*NBINS];
__device__ int   d_shash[BATCH*HSZ];
__device__ int   d_done[BATCH];
__device__ int   d_thr[BATCH];
__device__ int   d_ccnt[BATCH];
__device__ int   d_cpos[BATCH*CAP];
__device__ float d_cg[BATCH*CAP];
__device__ int   d_slp[BATCH*KSEL];           // shortlist: top-256 off-support by |g|
__device__ float d_slg[BATCH*KSEL];
__device__ float d_sg[BATCH*KSEL];            // g at support
__device__ float d_sx[BATCH*KSEL];            // x at support
__device__ int   d_selp[NAL*BATCH*KSEL];
__device__ float d_selv[NAL*BATCH*KSEL];
__device__ float d_errp[NAL*BATCH];
__device__ float d_l2p[BATCH];
__device__ int   d_supp[BATCH*KSEL];
__device__ int   d_nsup[BATCH];

__device__ __forceinline__ int binof(float g) {
    return (int)((__float_as_uint(g) & 0x7fffffffu) >> 19);
}

__device__ __forceinline__ int suffix_scan(int v, volatile int* wtmp, int nwarp) {
    int lane = threadIdx.x & 31, wid = threadIdx.x >> 5;
    int x = v;
    #pragma unroll
    for (int off = 1; off < 32; off <<= 1) {
        int u = __shfl_down_sync(0xffffffffu, x, off);
        if (lane + off < 32) x += u;
    }
    if (lane == 0) wtmp[wid] = x;
    __syncthreads();
    int add = 0;
    for (int j = wid + 1; j < nwarp; j++) add += wtmp[j];
    return x + add;
}

// ---------------- kernels ----------------

// zero X + state; iter-0 l2 = sum(Y^2) per sample
__global__ void k_init(float* __restrict__ X, const float* __restrict__ Y) {
    __shared__ float sred[8];
    int stride = gridDim.x * blockDim.x;
    int gid = blockIdx.x * blockDim.x + threadIdx.x;
    float4* X4 = (float4*)X;
    float4 z = make_float4(0.f, 0.f, 0.f, 0.f);
    for (int i = gid; i < BATCH*NPS/4; i += stride) X4[i] = z;
    for (int i = gid; i < BATCH*NBINS; i += stride) d_hist[i] = 0;
    for (int i = gid; i < BATCH*HSZ; i += stride) d_shash[i] = 0;
    if (gid < BATCH) {
        d_nsup[gid] = 0; d_ccnt[gid] = 0; d_done[gid] = 0;
    }
    if (blockIdx.x < BATCH) {
        int s = blockIdx.x, tid = threadIdx.x;
        float e = 0.f;
        for (int i = tid; i < IMGPIX; i += 256) {
            float r = Y[s*IMGPIX + i];
            e += r*r;
        }
        for (int o = 16; o; o >>= 1) e += __shfl_down_sync(0xffffffffu, e, o);
        if ((tid & 31) == 0) sred[tid >> 5] = e;
        __syncthreads();
        if (tid < 32) {
            e = (tid < 8) ? sred[tid] : 0.f;
            for (int o = 4; o; o >>= 1) e += __shfl_down_sync(0xffffffffu, e, o);
            if (tid == 0) d_l2p[s] = e;
        }
    }
}

// residual R = Y - conv_D(X_sparse); l2; support hash; zero hist/ccnt/done
__global__ void k_residual(const float* __restrict__ Y, const float* __restrict__ Wg,
                           const float* __restrict__ X) {
    __shared__ float syh[IMGPIX];
    __shared__ float sred[8];
    int s = blockIdx.x, tid = threadIdx.x;
    if (tid == 0) { d_ccnt[s] = 0; d_done[s] = 0; }
    int4* h4 = (int4*)&d_hist[s*NBINS];
    int4 z4 = make_int4(0,0,0,0);
    for (int i = tid; i < NBINS/4; i += 256) h4[i] = z4;
    for (int i = tid; i < HSZ; i += 256) d_shash[s*HSZ + i] = 0;
    for (int i = tid; i < IMGPIX; i += 256) syh[i] = 0.f;
    __syncthreads();
    int ns = d_nsup[s];
    if (tid < ns) {
        int pos = d_supp[s*KSEL + tid];
        if (pos >= 0) {
            float val = X[s*NPS + pos];
            int a = pos / SPP, rem = pos - a*SPP, u = rem / OH, v = rem - u*OH;
            const float* w = Wg + a*64;
            #pragma unroll
            for (int p = 0; p < 8; p++)
                #pragma unroll
                for (int q = 0; q < 8; q++)
                    atomicAdd(&syh[(u+p)*WW + v + q], val * w[p*8 + q]);
            unsigned h = ((unsigned)pos * 2654435761u >> 22) & (HSZ - 1);
            while (atomicCAS(&d_shash[s*HSZ + h], 0, pos + 1) != 0) h = (h + 1) & (HSZ - 1);
        }
    }
    __syncthreads();
    float e = 0.f;
    for (int i = tid; i < IMGPIX; i += 256) {
        float r = Y[s*IMGPIX + i] - syh[i];
        d_R[s*IMGPIX + i] = r;
        e += r*r;
    }
    for (int o = 16; o; o >>= 1) e += __shfl_down_sync(0xffffffffu, e, o);
    if ((tid & 31) == 0) sred[tid >> 5] = e;
    __syncthreads();
    if (tid < 32) {
        e = (tid < 8) ? sred[tid] : 0.f;
        for (int o = 4; o; o >>= 1) e += __shfl_down_sync(0xffffffffu, e, o);
        if (tid == 0) d_l2p[s] = e;
    }
}

// conv + hist + last-block threshold -> d_thr[s]. useY: iter 0 (R == Y).
__global__ void __launch_bounds__(256) k_conv_g(const float* __restrict__ Wg,
                                                const float* __restrict__ Y,
                                                int useY) {
    __shared__ float shR[39*64 + 16];
    __shared__ float shW[64*8];
    __shared__ int   shH[NBINS];
    __shared__ int   wtmp[8];
    __shared__ int   s_last;
    int bid = blockIdx.x;
    int s   = bid >> 5;
    int rem = bid & 31;
    int grp = rem >> 1;
    int uc  = rem & 1;
    int ub  = uc * 32;
    int abase = grp * 8;
    int tid = threadIdx.x;

    const float* src = useY ? Y : d_R;
    for (int i = tid; i < NBINS; i += 256) shH[i] = 0;
    for (int i = tid; i < 39*64; i += 256) {
        int r = ub + (i >> 6);
        shR[i] = (r < HH) ? src[s*IMGPIX + r*WW + (i & 63)] : 0.f;
    }
    if (tid < 16) shR[39*64 + tid] = 0.f;
    for (int i = tid; i < 512; i += 256) {
        int a = i & 7, pq = i >> 3, p = pq >> 3, q = pq & 7;
        shW[pq*8 + a] = Wg[(abase + a)*64 + q*8 + p];
    }
    __syncthreads();

    int v  = tid & 63;
    int ty = tid >> 6;
    int u0 = ty * 8;

    ull acc[4][8];
    #pragma unroll
    for (int ap = 0; ap < 4; ap++)
        #pragma unroll
        for (int uu = 0; uu < 8; uu++) acc[ap][uu] = 0ull;

    #pragma unroll 1
    for (int p = 0; p < 8; p++) {
        #pragma unroll
        for (int q = 0; q < 8; q++) {
            ull w2[4];
            const ull* wrow = (const ull*)&shW[(p*8 + q)*8];
            #pragma unroll
            for (int ap = 0; ap < 4; ap++) w2[ap] = wrow[ap];
            #pragma unroll
            for (int uu = 0; uu < 8; uu++) {
                float r = shR[(u0 + uu + p)*64 + v + q];
                ull r2;
                asm("mov.b64 %0, {%1, %1};" : "=l"(r2) : "f"(r));
                #pragma unroll
                for (int ap = 0; ap < 4; ap++)
                    asm("fma.rn.f32x2 %0, %1, %2, %0;"
                        : "+l"(acc[ap][uu]) : "l"(w2[ap]), "l"(r2));
            }
        }
    }

    bool vok = (v < OH);
    #pragma unroll
    for (int uu = 0; uu < 8; uu++) {
        int u = ub + u0 + uu;
        if (vok && u < OH) {
            int base = s*NPS + abase*SPP + u*OH + v;
            #pragma unroll
            for (int ap = 0; ap < 4; ap++) {
                float lo, hi;
                asm("mov.b64 {%0, %1}, %2;" : "=f"(lo), "=f"(hi) : "l"(acc[ap][uu]));
                d_g[base + (2*ap)*SPP]   = lo;
                d_g[base + (2*ap+1)*SPP] = hi;
                atomicAdd(&shH[binof(lo)], 1);
                atomicAdd(&shH[binof(hi)], 1);
            }
        }
    }
    __syncthreads();
    for (int i = tid; i < NBINS; i += 256)
        if (shH[i]) atomicAdd(&d_hist[s*NBINS + i], shH[i]);
    __threadfence();
    __syncthreads();
    if (tid == 0) {
        int r = atomicAdd(&d_done[s], 1);
        s_last = (r == 31) ? 1 : 0;
    }
    __syncthreads();
    if (s_last) {
        __threadfence();
        const int* hist = &d_hist[s*NBINS];
        int seg = 0;
        #pragma unroll
        for (int j = 0; j < 16; j++) seg += hist[tid*16 + j];
        int ss = suffix_scan(seg, wtmp, 8);
        int low = ss - seg;
        if (ss >= 2*KSEL && low < 2*KSEL) {
            int cum = low;
            for (int j = 15; j >= 0; j--) {
                cum += hist[tid*16 + j];
                if (cum >= 2*KSEL) { d_thr[s] = tid*16 + j; break; }
            }
        }
    }
}

// chunks 0..50: dense g scan (pos+g only); chunk 51: fill support g/x arrays.
__global__ void __launch_bounds__(256) k_collect(const float* __restrict__ X) {
    int s = blockIdx.y, chunk = blockIdx.x, tid = threadIdx.x;

    if (chunk == 51) {
        int ns = d_nsup[s];
        if (tid < ns) {
            int pos = d_supp[s*KSEL + tid];
            if (pos >= 0) {
                d_sg[s*KSEL + tid] = d_g[s*NPS + pos];
                d_sx[s*KSEL + tid] = X[s*NPS + pos];
            } else {
                d_sg[s*KSEL + tid] = 0.f;
                d_sx[s*KSEL + tid] = 0.f;
            }
        }
        return;
    }
    int thr = d_thr[s];
    unsigned thrbits = (unsigned)thr << 19;

    const float4* g4 = (const float4*)&d_g[s*NPS];
    int base = chunk * VCHUNK;
    int end = base + VCHUNK; if (end > NVEC) end = NVEC;
    int i = base + tid;
    for (; i + 768 < end; i += 1024) {
        float4 a = g4[i];
        float4 b = g4[i + 256];
        float4 c = g4[i + 512];
        float4 d = g4[i + 768];
        float va[16] = {a.x,a.y,a.z,a.w, b.x,b.y,b.z,b.w,
                        c.x,c.y,c.z,c.w, d.x,d.y,d.z,d.w};
        #pragma unroll
        for (int l = 0; l < 16; l++) {
            if ((__float_as_uint(va[l]) & 0x7fffffffu) >= thrbits) {
                int pos = (i + (l >> 2)*256)*4 + (l & 3);
                int idx = atomicAdd(&d_ccnt[s], 1);
                if (idx < CAP) {
                    d_cpos[s*CAP + idx] = pos;
                    d_cg[s*CAP + idx]   = va[l];
                }
            }
        }
    }
    for (; i < end; i += 256) {
        float4 a = g4[i];
        float va[4] = {a.x, a.y, a.z, a.w};
        #pragma unroll
        for (int l = 0; l < 4; l++) {
            if ((__float_as_uint(va[l]) & 0x7fffffffu) >= thrbits) {
                int pos = i*4 + l;
                int idx = atomicAdd(&d_ccnt[s], 1);
                if (idx < CAP) {
                    d_cpos[s*CAP + idx] = pos;
                    d_cg[s*CAP + idx]   = va[l];
                }
            }
        }
    }
}

// once per sample: top-256 OFF-SUPPORT candidates by (|g|,~pos) key (alpha-invariant)
__global__ void __launch_bounds__(512) k_shortlist() {
    __shared__ ull skey[CAP];
    __shared__ int s_cnt;
    int s = blockIdx.x, tid = threadIdx.x;
    int n = d_ccnt[s]; if (n > CAP) n = CAP;
    const int* shash = &d_shash[s*HSZ];

    for (int i = tid; i < n; i += 512) {
        int pos = d_cpos[s*CAP + i];
        unsigned h = ((unsigned)pos * 2654435761u >> 22) & (HSZ - 1);
        bool insup = false;
        while (true) {
            int hv = shash[h];
            if (hv == 0) break;
            if (hv == pos + 1) { insup = true; break; }
            h = (h + 1) & (HSZ - 1);
        }
        ull k = 0ull;
        if (!insup) {
            unsigned ab = __float_as_uint(d_cg[s*CAP + i]) & 0x7fffffffu;
            k = ((ull)ab << 19) | (unsigned)((~pos) & 0x7ffff);
        }
        skey[i] = k;
    }
    if (tid == 0) s_cnt = 0;
    __syncthreads();

    ull mykey[4]; int myi[4]; int cnt[4];
    int ne = 0;
    for (int i = tid; i < n; i += 512) { mykey[ne] = skey[i]; myi[ne] = i; cnt[ne] = 0; ne++; }
    for (int j = 0; j < n; j++) {
        ull k = skey[j];
        #pragma unroll
        for (int e = 0; e < 4; e++)
            if (e < ne) cnt[e] += (k > mykey[e]);
    }
    for (int e = 0; e < ne; e++) {
        if (mykey[e] != 0ull && cnt[e] < KSEL) {
            int slot = atomicAdd(&s_cnt, 1);
            int i = myi[e];
            d_slp[s*KSEL + slot] = d_cpos[s*CAP + i];
            d_slg[s*KSEL + slot] = d_cg[s*CAP + i];
        }
    }
}

// one block per (alpha, sample): 512-entry rank-count select, bucketed gather, err
__global__ void __launch_bounds__(512) k_attempt(const float* __restrict__ Y,
                                                 const float* __restrict__ Wg) {
    __shared__ ull   skey[512];
    __shared__ float sred[16];
    __shared__ unsigned spk[KSEL];
    __shared__ float spv[KSEL];
    __shared__ int   rcnt[64];
    __shared__ int   s_cnt;
    __shared__ unsigned char lists[64*256];

    int ka = blockIdx.x, s = blockIdx.y, tid = threadIdx.x;
    float alpha = 1.0f / (float)(1 << ka);
    int ns = d_nsup[s];

    ull mykey = 0ull; float myval = 0.f; int mypos = -1;
    if (tid < KSEL) {
        mypos = d_slp[s*KSEL + tid];
        myval = alpha * d_slg[s*KSEL + tid];
        unsigned ab = __float_as_uint(myval) & 0x7fffffffu;
        mykey = ((ull)ab << 19) | (unsigned)((~mypos) & 0x7ffff);
    } else {
        int j = tid - KSEL;
        if (j < ns) {
            int pos = d_supp[s*KSEL + j];
            if (pos >= 0) {
                mypos = pos;
                myval = d_sx[s*KSEL + j] + alpha * d_sg[s*KSEL + j];
                unsigned ab = __float_as_uint(myval) & 0x7fffffffu;
                mykey = ((ull)ab << 19) | (unsigned)((~mypos) & 0x7ffff);
            }
        }
    }
    skey[tid] = mykey;
    if (tid < 64) rcnt[tid] = 0;
    if (tid == 0) s_cnt = 0;
    __syncthreads();

    int cnt = 0;
    #pragma unroll 8
    for (int j = 0; j < 512; j++) cnt += (skey[j] > mykey);

    int selbase = (ka*BATCH + s)*KSEL;
    bool sel = (mykey != 0ull) && (cnt < KSEL);
    int slot = -1; int su = 0, sv = 0;
    if (sel) {
        slot = atomicAdd(&s_cnt, 1);
        d_selp[selbase + slot] = mypos;
        d_selv[selbase + slot] = myval;
        int a = mypos / SPP, rem2 = mypos - a*SPP;
        su = rem2 / OH; sv = rem2 - su*OH;
        spk[slot] = ((unsigned)a << 12) | ((unsigned)su << 6) | (unsigned)sv;
        spv[slot] = myval;
    }
    __syncthreads();
    if (sel) {
        #pragma unroll
        for (int p = 0; p < 8; p++) {
            int bs = atomicAdd(&rcnt[su + p], 1);
            lists[(su + p)*256 + bs] = (unsigned char)slot;
        }
    }
    __syncthreads();

    // ownership gather: thread owns row r, cols [c0, c0+8)
    int r  = tid >> 3;
    int c0 = (tid & 7) << 3;
    int nr = rcnt[r];
    const unsigned char* mylist = lists + r*256;
    float acc[8];
    #pragma unroll
    for (int j = 0; j < 8; j++) acc[j] = 0.f;

    for (int t = 0; t < nr; t++) {
        int c = (int)mylist[t];
        unsigned pk = spk[c];
        int v = (int)(pk & 63u);
        if (v <= c0 + 7 && v + 7 >= c0) {
            float val = spv[c];
            int du = r - (int)((pk >> 6) & 63u);
            const float* wrow = Wg + ((pk >> 12) << 6) + du*8;
            #pragma unroll
            for (int j = 0; j < 8; j++) {
                int q = c0 + j - v;
                if (q >= 0 && q < 8)
                    acc[j] = fmaf(val, __ldg(wrow + q), acc[j]);
            }
        }
    }

    float e = 0.f;
    const float* yrow = Y + s*IMGPIX + r*WW + c0;
    #pragma unroll
    for (int j = 0; j < 8; j++) {
        float d = yrow[j] - acc[j];
        e += d*d;
    }
    for (int o = 16; o; o >>= 1) e += __shfl_down_sync(0xffffffffu, e, o);
    if ((tid & 31) == 0) sred[tid >> 5] = e;
    __syncthreads();
    if (tid < 32) {
        e = (tid < 16) ? sred[tid] : 0.f;
        for (int o = 8; o; o >>= 1) e += __shfl_down_sync(0xffffffffu, e, o);
        if (tid == 0) d_errp[ka*BATCH + s] = e;
    }
}

// commit: parallel redundant alpha choice, scatter-update X + support
__global__ void k_commit(float* __restrict__ X) {
    __shared__ float serr[NAL];
    __shared__ float sl2;
    __shared__ int sc;
    int s = blockIdx.x, tid = threadIdx.x;
    if (tid < NAL) {
        float e = 0.f;
        for (int s2 = 0; s2 < BATCH; s2++) e += d_errp[tid*BATCH + s2];
        serr[tid] = e;
    }
    if (tid == 32) {
        float l2 = 0.f;
        for (int s2 = 0; s2 < BATCH; s2++) l2 += d_l2p[s2];
        sl2 = l2;
    }
    __syncthreads();
    if (tid == 0) {
        int c = NAL - 1;
        for (int k = 0; k < NAL; k++)
            if (serr[k] < sl2) { c = k; break; }
        sc = c;
    }
    int ns = d_nsup[s];
    if (tid < ns) {
        int p = d_supp[s*KSEL + tid];
        if (p >= 0) X[s*NPS + p] = 0.f;
    }
    __syncthreads();
    int c = sc;
    int pos = d_selp[(c*BATCH + s)*KSEL + tid];
    float val = d_selv[(c*BATCH + s)*KSEL + tid];
    if (pos >= 0) X[s*NPS + pos] = val;
    d_supp[s*KSEL + tid] = pos;
    if (tid == 0) d_nsup[s] = KSEL;
}

// ---------------- launch ----------------
extern "C" void kernel_launch(void* const* d_in, const int* in_sizes, int n_in,
                              void* d_out, int out_size) {
    const float* Y  = (const float*)d_in[0];
    const float* Wg = (const float*)d_in[1];
    float* X = (float*)d_out;

    k_init<<<2048, 256>>>(X, Y);
    for (int it = 0; it < 3; it++) {
        if (it) k_residual<<<BATCH, 256>>>(Y, Wg, X);
        k_conv_g<<<1024, 256>>>(Wg, Y, it == 0 ? 1 : 0);
        k_collect<<<dim3(52, BATCH), 256>>>(X);
        k_shortlist<<<BATCH, 512>>>();
        k_attempt<<<dim3(NAL, BATCH), 512>>>(Y, Wg);
        k_commit<<<BATCH, KSEL>>>(X);
    }
}

// round 17
// speedup vs baseline: 1.3584x; 1.3584x over previous
#include <cuda_runtime.h>

typedef unsigned long long ull;

#define BATCH 32
#define NATOM 128
#define HH 64
#define WW 64
#define OH 57
#define SPP (OH*OH)           // 3249
#define NPS (NATOM*SPP)       // 415872
#define KSEL 256
#define NAL 17
#define CAP 1024
#define NBINS 4096
#define IMGPIX (HH*WW)        // 4096
#define NVEC (NPS/4)          // 103968 float4s
#define VCHUNK 2048           // float4s per collect chunk (51 chunks)

// ---------------- device state ----------------
__device__ float d_R[BATCH*IMGPIX];
__device__ float d_g[BATCH*NPS];              // ~53 MB
__device__ int   d_hist[BATCH*NBINS];
__device__ int   d_done[BATCH];
__device__ int   d_thr[BATCH];
__device__ int   d_ccnt[BATCH];
__device__ int   d_cpos[BATCH*CAP];
__device__ float d_cg[BATCH*CAP];
__device__ float d_cx[BATCH*CAP];
__device__ int   d_selp[NAL*BATCH*KSEL];
__device__ float d_selv[NAL*BATCH*KSEL];
__device__ float d_errp[NAL*BATCH];
__device__ float d_l2p[BATCH];
__device__ int   d_supp[BATCH*KSEL];
__device__ int   d_nsup[BATCH];

__device__ __forceinline__ int binof(float g) {
    return (int)((__float_as_uint(g) & 0x7fffffffu) >> 19);
}

// inclusive suffix sum over blockDim.x per-thread values
__device__ __forceinline__ int suffix_scan(int v, volatile int* wtmp, int nwarp) {
    int lane = threadIdx.x & 31, wid = threadIdx.x >> 5;
    int x = v;
    #pragma unroll
    for (int off = 1; off < 32; off <<= 1) {
        int u = __shfl_down_sync(0xffffffffu, x, off);
        if (lane + off < 32) x += u;
    }
    if (lane == 0) wtmp[wid] = x;
    __syncthreads();
    int add = 0;
    for (int j = wid + 1; j < nwarp; j++) add += wtmp[j];
    return x + add;
}

// ---------------- kernels ----------------

__global__ void k_init(float* __restrict__ X) {
    float4* X4 = (float4*)X;
    int stride = gridDim.x * blockDim.x;
    float4 z = make_float4(0.f, 0.f, 0.f, 0.f);
    for (int i = blockIdx.x * blockDim.x + threadIdx.x; i < BATCH*NPS/4; i += stride)
        X4[i] = z;
    if (blockIdx.x == 0 && threadIdx.x < BATCH) {
        d_nsup[threadIdx.x] = 0;
        d_done[threadIdx.x] = 0;
    }
}

// residual R = Y - conv_D(X_sparse); per-sample l2; zero hist/ccnt/done
__global__ void k_residual(const float* __restrict__ Y, const float* __restrict__ Wg,
                           const float* __restrict__ X) {
    __shared__ float syh[IMGPIX];
    __shared__ float sred[8];
    int s = blockIdx.x, tid = threadIdx.x;
    if (tid == 0) { d_ccnt[s] = 0; d_done[s] = 0; }
    int4* h4 = (int4*)&d_hist[s*NBINS];
    int4 z4 = make_int4(0,0,0,0);
    for (int i = tid; i < NBINS/4; i += 256) h4[i] = z4;
    for (int i = tid; i < IMGPIX; i += 256) syh[i] = 0.f;
    __syncthreads();
    int ns = d_nsup[s];
    if (tid < ns) {
        int pos = d_supp[s*KSEL + tid];
        if (pos >= 0) {
            float val = X[s*NPS + pos];
            int a = pos / SPP, rem = pos - a*SPP, u = rem / OH, v = rem - u*OH;
            const float* w = Wg + a*64;
            #pragma unroll
            for (int p = 0; p < 8; p++)
                #pragma unroll
                for (int q = 0; q < 8; q++)
                    atomicAdd(&syh[(u+p)*WW + v + q], val * w[p*8 + q]);
        }
    }
    __syncthreads();
    float e = 0.f;
    for (int i = tid; i < IMGPIX; i += 256) {
        float r = Y[s*IMGPIX + i] - syh[i];
        d_R[s*IMGPIX + i] = r;
        e += r*r;
    }
    for (int o = 16; o; o >>= 1) e += __shfl_down_sync(0xffffffffu, e, o);
    if ((tid & 31) == 0) sred[tid >> 5] = e;
    __syncthreads();
    if (tid < 32) {
        e = (tid < 8) ? sred[tid] : 0.f;
        for (int o = 4; o; o >>= 1) e += __shfl_down_sync(0xffffffffu, e, o);
        if (tid == 0) d_l2p[s] = e;
    }
}

// g[b,a,u,v] = sum_{p,q} R[b,u+p,v+q] * W[a,q,p]; fused |g| histogram +
// last-block-per-sample threshold computation -> d_thr[s].
__global__ void __launch_bounds__(256) k_conv_g(const float* __restrict__ Wg) {
    __shared__ float shR[39*64 + 16];
    __shared__ float shW[64*8];       // [p*8+q][a]
    __shared__ int   shH[NBINS];
    __shared__ int   wtmp[8];
    __shared__ int   s_last;
    int bid = blockIdx.x;
    int s   = bid >> 5;
    int rem = bid & 31;
    int grp = rem >> 1;
    int uc  = rem & 1;
    int ub  = uc * 32;
    int abase = grp * 8;
    int tid = threadIdx.x;

    for (int i = tid; i < NBINS; i += 256) shH[i] = 0;
    for (int i = tid; i < 39*64; i += 256) {
        int r = ub + (i >> 6);
        shR[i] = (r < HH) ? d_R[s*IMGPIX + r*WW + (i & 63)] : 0.f;
    }
    if (tid < 16) shR[39*64 + tid] = 0.f;
    for (int i = tid; i < 512; i += 256) {
        int a = i & 7, pq = i >> 3, p = pq >> 3, q = pq & 7;
        shW[pq*8 + a] = Wg[(abase + a)*64 + q*8 + p];
    }
    __syncthreads();

    int v  = tid & 63;
    int ty = tid >> 6;
    int u0 = ty * 8;

    ull acc[4][8];
    #pragma unroll
    for (int ap = 0; ap < 4; ap++)
        #pragma unroll
        for (int uu = 0; uu < 8; uu++) acc[ap][uu] = 0ull;

    #pragma unroll 1
    for (int p = 0; p < 8; p++) {
        #pragma unroll
        for (int q = 0; q < 8; q++) {
            ull w2[4];
            const ull* wrow = (const ull*)&shW[(p*8 + q)*8];
            #pragma unroll
            for (int ap = 0; ap < 4; ap++) w2[ap] = wrow[ap];
            #pragma unroll
            for (int uu = 0; uu < 8; uu++) {
                float r = shR[(u0 + uu + p)*64 + v + q];
                ull r2;
                asm("mov.b64 %0, {%1, %1};" : "=l"(r2) : "f"(r));
                #pragma unroll
                for (int ap = 0; ap < 4; ap++)
                    asm("fma.rn.f32x2 %0, %1, %2, %0;"
                        : "+l"(acc[ap][uu]) : "l"(w2[ap]), "l"(r2));
            }
        }
    }

    bool vok = (v < OH);
    #pragma unroll
    for (int uu = 0; uu < 8; uu++) {
        int u = ub + u0 + uu;
        if (vok && u < OH) {
            int base = s*NPS + abase*SPP + u*OH + v;
            #pragma unroll
            for (int ap = 0; ap < 4; ap++) {
                float lo, hi;
                asm("mov.b64 {%0, %1}, %2;" : "=f"(lo), "=f"(hi) : "l"(acc[ap][uu]));
                d_g[base + (2*ap)*SPP]   = lo;
                d_g[base + (2*ap+1)*SPP] = hi;
                atomicAdd(&shH[binof(lo)], 1);
                atomicAdd(&shH[binof(hi)], 1);
            }
        }
    }
    __syncthreads();
    for (int i = tid; i < NBINS; i += 256)
        if (shH[i]) atomicAdd(&d_hist[s*NBINS + i], shH[i]);
    __threadfence();
    __syncthreads();
    if (tid == 0) {
        int r = atomicAdd(&d_done[s], 1);
        s_last = (r == 31) ? 1 : 0;
    }
    __syncthreads();
    if (s_last) {
        __threadfence();
        const int* hist = &d_hist[s*NBINS];
        int seg = 0;
        #pragma unroll
        for (int j = 0; j < 16; j++) seg += hist[tid*16 + j];
        int ss = suffix_scan(seg, wtmp, 8);
        int low = ss - seg;
        if (ss >= 2*KSEL && low < 2*KSEL) {
            int cum = low;
            for (int j = 15; j >= 0; j--) {
                cum += hist[tid*16 + j];
                if (cum >= 2*KSEL) { d_thr[s] = tid*16 + j; break; }
            }
        }
    }
}

// grid (52, 32): chunks 0..50 scan dense g (4-deep float4) against d_thr[s];
// chunk 51 appends support entries below threshold.
__global__ void __launch_bounds__(256) k_collect(const float* __restrict__ X) {
    int s = blockIdx.y, chunk = blockIdx.x, tid = threadIdx.x;
    int thr = d_thr[s];
    unsigned thrbits = (unsigned)thr << 19;

    if (chunk == 51) {
        int ns = d_nsup[s];
        if (tid < ns) {
            int pos = d_supp[s*KSEL + tid];
            if (pos >= 0) {
                float gv = d_g[s*NPS + pos];
                if ((__float_as_uint(gv) & 0x7fffffffu) < thrbits) {
                    int idx = atomicAdd(&d_ccnt[s], 1);
                    if (idx < CAP) {
                        d_cpos[s*CAP + idx] = pos;
                        d_cg[s*CAP + idx]   = gv;
                        d_cx[s*CAP + idx]   = X[s*NPS + pos];
                    }
                }
            }
        }
        return;
    }

    const float4* g4 = (const float4*)&d_g[s*NPS];
    int base = chunk * VCHUNK;
    int end = base + VCHUNK; if (end > NVEC) end = NVEC;
    int i = base + tid;
    for (; i + 768 < end; i += 1024) {
        float4 a = g4[i];
        float4 b = g4[i + 256];
        float4 c = g4[i + 512];
        float4 d = g4[i + 768];
        float va[16] = {a.x,a.y,a.z,a.w, b.x,b.y,b.z,b.w,
                        c.x,c.y,c.z,c.w, d.x,d.y,d.z,d.w};
        #pragma unroll
        for (int l = 0; l < 16; l++) {
            if ((__float_as_uint(va[l]) & 0x7fffffffu) >= thrbits) {
                int pos = (i + (l >> 2)*256)*4 + (l & 3);
                int idx = atomicAdd(&d_ccnt[s], 1);
                if (idx < CAP) {
                    d_cpos[s*CAP + idx] = pos;
                    d_cg[s*CAP + idx]   = va[l];
                    d_cx[s*CAP + idx]   = X[s*NPS + pos];
                }
            }
        }
    }
    for (; i < end; i += 256) {
        float4 a = g4[i];
        float va[4] = {a.x, a.y, a.z, a.w};
        #pragma unroll
        for (int l = 0; l < 4; l++) {
            if ((__float_as_uint(va[l]) & 0x7fffffffu) >= thrbits) {
                int pos = i*4 + l;
                int idx = atomicAdd(&d_ccnt[s], 1);
                if (idx < CAP) {
                    d_cpos[s*CAP + idx] = pos;
                    d_cg[s*CAP + idx]   = va[l];
                    d_cx[s*CAP + idx]   = X[s*NPS + pos];
                }
            }
        }
    }
}

// one block per (alpha, sample): exact top-256 via radix-select over 51-bit keys
// (shifts 39/27/15/3 x 12 bits + final 3 bits), then row-bucketed register gather.
// CAP=1024 keeps smem at ~31 KB -> 4 blocks/SM (full occupancy, single wave).
__global__ void __launch_bounds__(512) k_attempt(const float* __restrict__ Y,
                                                 const float* __restrict__ Wg) {
    __shared__ ull   skey[CAP];
    __shared__ float sval[CAP];
    __shared__ unsigned aux[NBINS];   // radix digit hist; then uint8 row lists [64][256]
    __shared__ int   wtmp[16];
    __shared__ ull   s_prefix, s_T;
    __shared__ int   s_m, s_done, s_cnt;
    __shared__ float sred[16];
    __shared__ unsigned spk[KSEL];    // packed a<<12 | u<<6 | v
    __shared__ float spv[KSEL];
    __shared__ int   rcnt[64];

    int ka = blockIdx.x, s = blockIdx.y, tid = threadIdx.x;
    float alpha = 1.0f / (float)(1 << ka);
    int n = d_ccnt[s]; if (n > CAP) n = CAP;

    for (int i = tid; i < n; i += 512) {
        int pos = d_cpos[s*CAP + i];
        float val = d_cx[s*CAP + i] + alpha * d_cg[s*CAP + i];
        unsigned ab = __float_as_uint(val) & 0x7fffffffu;
        skey[i] = ((ull)ab << 19) | (unsigned)((~pos) & 0x7ffff);
        sval[i] = val;
    }
    if (tid == 0) { s_prefix = 0ull; s_m = KSEL; s_done = (n <= KSEL) ? 1 : 0; s_T = 1ull; }

    const int shifts[5] = {39, 27, 15, 3, 0};
    const int widths[5] = {12, 12, 12, 12, 3};
    #pragma unroll 1
    for (int lvl = 0; lvl < 5; lvl++) {
        __syncthreads();
        int done = s_done; ull pref = s_prefix; int m = s_m;
        int shift = shifts[lvl];
        unsigned dmask = (1u << widths[lvl]) - 1u;
        if (!done) {
            for (int i = tid; i < NBINS; i += 512) aux[i] = 0u;
            __syncthreads();
            ull himask = ~(((ull)1 << (shift + widths[lvl])) - 1);
            for (int i = tid; i < n; i += 512) {
                ull k = skey[i];
                if ((k & himask) == pref)
                    atomicAdd(&aux[(unsigned)(k >> shift) & dmask], 1u);
            }
            __syncthreads();
            int seg = 0;
            #pragma unroll
            for (int j = 0; j < 8; j++) seg += (int)aux[tid*8 + j];
            int ss = suffix_scan(seg, wtmp, 16);
            int low = ss - seg;
            if (ss >= m && low < m) {
                int cum = low, b = tid*8, h_b = 0;
                for (int j = 7; j >= 0; j--) {
                    int c = (int)aux[tid*8 + j];
                    cum += c;
                    if (cum >= m) { b = tid*8 + j; h_b = c; break; }
                }
                ull npref = pref | ((ull)b << shift);
                if (cum == m || shift == 0) { s_T = npref; s_done = 1; }
                else { s_prefix = npref; s_m = m - (cum - h_b); }
            }
        } else {
            __syncthreads();
        }
    }
    __syncthreads();
    ull T = s_T;

    int selbase = (ka*BATCH + s)*KSEL;
    if (tid < KSEL) d_selp[selbase + tid] = -1;
    if (tid < 64) rcnt[tid] = 0;
    if (tid == 0) s_cnt = 0;
    __syncthreads();

    for (int i = tid; i < n; i += 512) {
        ull k = skey[i];
        if (k >= T) {
            int slot = atomicAdd(&s_cnt, 1);
            int pos = (int)((~(unsigned)k) & 0x7ffff);
            float val = sval[i];
            d_selp[selbase + slot] = pos;
            d_selv[selbase + slot] = val;
            int a = pos / SPP, rem2 = pos - a*SPP, u = rem2 / OH, v = rem2 - u*OH;
            spk[slot] = ((unsigned)a << 12) | ((unsigned)u << 6) | (unsigned)v;
            spv[slot] = val;
        }
    }
    __syncthreads();
    int cnt = s_cnt; if (cnt > KSEL) cnt = KSEL;

    // bucket entries by output row (entry at u covers rows u..u+7, all < 64)
    unsigned char* lists = (unsigned char*)aux;   // [64][256]
    for (int c = tid; c < cnt; c += 512) {
        int u = (int)((spk[c] >> 6) & 63u);
        #pragma unroll
        for (int p = 0; p < 8; p++) {
            int slot = atomicAdd(&rcnt[u + p], 1);
            lists[(u + p)*256 + slot] = (unsigned char)c;
        }
    }
    __syncthreads();

    // ownership gather: thread owns row r, cols [c0, c0+8)
    int r  = tid >> 3;
    int c0 = (tid & 7) << 3;
    int nr = rcnt[r];
    const unsigned char* mylist = lists + r*256;
    float acc[8];
    #pragma unroll
    for (int j = 0; j < 8; j++) acc[j] = 0.f;

    for (int t = 0; t < nr; t++) {
        int c = (int)mylist[t];
        unsigned pk = spk[c];
        int v = (int)(pk & 63u);
        if (v <= c0 + 7 && v + 7 >= c0) {
            float val = spv[c];
            int du = r - (int)((pk >> 6) & 63u);
            const float* wrow = Wg + ((pk >> 12) << 6) + du*8;
            #pragma unroll
            for (int j = 0; j < 8; j++) {
                int q = c0 + j - v;
                if (q >= 0 && q < 8)
                    acc[j] = fmaf(val, __ldg(wrow + q), acc[j]);
            }
        }
    }

    float e = 0.f;
    const float* yrow = Y + s*IMGPIX + r*WW + c0;
    #pragma unroll
    for (int j = 0; j < 8; j++) {
        float d = yrow[j] - acc[j];
        e += d*d;
    }
    for (int o = 16; o; o >>= 1) e += __shfl_down_sync(0xffffffffu, e, o);
    if ((tid & 31) == 0) sred[tid >> 5] = e;
    __syncthreads();
    if (tid < 32) {
        e = (tid < 16) ? sred[tid] : 0.f;
        for (int o = 8; o; o >>= 1) e += __shfl_down_sync(0xffffffffu, e, o);
        if (tid == 0) d_errp[ka*BATCH + s] = e;
    }
}

// commit: parallel redundant alpha choice, scatter-update X + support
__global__ void k_commit(float* __restrict__ X) {
    __shared__ float serr[NAL];
    __shared__ float sl2;
    __shared__ int sc;
    int s = blockIdx.x, tid = threadIdx.x;
    if (tid < NAL) {
        float e = 0.f;
        for (int s2 = 0; s2 < BATCH; s2++) e += d_errp[tid*BATCH + s2];
        serr[tid] = e;
    }
    if (tid == 32) {
        float l2 = 0.f;
        for (int s2 = 0; s2 < BATCH; s2++) l2 += d_l2p[s2];
        sl2 = l2;
    }
    __syncthreads();
    if (tid == 0) {
        int c = NAL - 1;
        for (int k = 0; k < NAL; k++)
            if (serr[k] < sl2) { c = k; break; }
        sc = c;
    }
    int ns = d_nsup[s];
    if (tid < ns) {
        int p = d_supp[s*KSEL + tid];
        if (p >= 0) X[s*NPS + p] = 0.f;
    }
    __syncthreads();
    int c = sc;
    int pos = d_selp[(c*BATCH + s)*KSEL + tid];
    float val = d_selv[(c*BATCH + s)*KSEL + tid];
    if (pos >= 0) X[s*NPS + pos] = val;
    d_supp[s*KSEL + tid] = pos;
    if (tid == 0) d_nsup[s] = KSEL;
}

// ---------------- launch ----------------
extern "C" void kernel_launch(void* const* d_in, const int* in_sizes, int n_in,
                              void* d_out, int out_size) {
    const float* Y  = (const float*)d_in[0];
    const float* Wg = (const float*)d_in[1];
    float* X = (float*)d_out;

    k_init<<<2048, 256>>>(X);
    for (int it = 0; it < 3; it++) {
        k_residual<<<BATCH, 256>>>(Y, Wg, X);
        k_conv_g<<<1024, 256>>>(Wg);
        k_collect<<<dim3(52, BATCH), 256>>>(X);
        k_attempt<<<dim3(NAL, BATCH), 512>>>(Y, Wg);
        k_commit<<<BATCH, KSEL>>>(X);
    }
}